// round 12
// baseline (speedup 1.0000x reference)
#include <cuda_runtime.h>
#include <math.h>

#define PS 16
#define NB 32
#define IW 1024
#define IMGSZ (1024*1024)
#define NPATCH 4096
#define NBANDS 4
#define BPH 16                    // patch rows per band
#define NU 2048                   // units per phase per band = 32 b * 16 sy * 4 qtr

// Persistent-kernel global state (zero-initialized once; counters are reset
// by barrier masters at end of use so every launch starts clean).
__device__ float    g_s [NPATCH * NB];   // [patch][b] raw sum
__device__ float    g_s2[NPATCH * NB];   // [patch][b] raw sumsq
__device__ int      g_tick[2 * NBANDS];  // [band]=stats, [4+band]=apply
__device__ unsigned g_count;
__device__ volatile unsigned g_epoch;

__device__ __forceinline__ float clamp01(float x) {
    return fminf(fmaxf(x, 0.0f), 1.0f);
}

// Grid-wide barrier (sense-reversing epoch). All G CTAs are resident by
// construction (grid = SMs * occupancy), so this cannot deadlock.
// The master additionally resets `reset_lo..reset_hi` ticket counters.
__device__ void gbar(int G, int reset_lo, int reset_hi) {
    __threadfence();              // publish this thread's prior stores
    __syncthreads();
    if (threadIdx.x == 0) {
        unsigned e = g_epoch;
        unsigned old = atomicAdd(&g_count, 1u);
        if (old == (unsigned)(G - 1)) {
            for (int i = reset_lo; i <= reset_hi; ++i) g_tick[i] = 0;
            g_count = 0;
            __threadfence();
            g_epoch = e + 1;      // release
        } else {
            while (g_epoch == e) __nanosleep(64);
            __threadfence();      // acquire
        }
    }
    __syncthreads();
}

// ---------------------------------------------------------------------------
// Persistent kernel: for each 32MB band: [stats units] -> barrier ->
// [apply units]. Tickets balance stats (which gate the barrier); apply
// stragglers are absorbed by the next band's stats tickets.
// Unit = (b, sy, quarter): 256 threads, thread = one column of a 16x256
// strip. All global accesses are dense 128B warp lines (proven 5.9 TB/s).
// Apply reads hit L2 (band just streamed by stats).
// ---------------------------------------------------------------------------
__global__ void __launch_bounds__(256)
persist_kernel(const float* __restrict__ img,
               const float* __restrict__ noise,
               const float* __restrict__ r_strong,
               const float* __restrict__ r_drop,
               const float* __restrict__ r_else,
               const float* __restrict__ bright_f,
               const float* __restrict__ contrast_f,
               const float* __restrict__ slight_f,
               const int*   __restrict__ aug_choice,
               const int*   __restrict__ slight_choice,
               float* __restrict__ out, int G) {
    __shared__ int   s_u;
    __shared__ int   s_code[16];
    __shared__ float s_al[16], s_be[16], s_de[16];

    const int tx = threadIdx.x;

    for (int band = 0; band < NBANDS; ++band) {
        // ================= STATS phase (ticketed) =================
        for (;;) {
            if (tx == 0) s_u = atomicAdd(&g_tick[band], 1);
            __syncthreads();
            const int u = s_u;
            __syncthreads();
            if (u >= NU) break;

            const int qtr = u & 3;
            const int sy  = band * BPH + ((u >> 2) & 15);
            const int b   = u >> 6;
            const int x   = qtr * 256 + tx;
            const float* base = img + (size_t)b * IMGSZ + (size_t)(sy * PS) * IW + x;

            float s = 0.f, ss = 0.f;
#pragma unroll
            for (int y = 0; y < PS; ++y) {
                float v = base[(size_t)y * IW];
                s += v;
                ss = fmaf(v, v, ss);
            }
#pragma unroll
            for (int off = 8; off >= 1; off >>= 1) {
                s  += __shfl_down_sync(0xffffffffu, s,  off, 16);
                ss += __shfl_down_sync(0xffffffffu, ss, off, 16);
            }
            if ((tx & 15) == 0) {
                const int pg = sy * 64 + (x >> 4);
                g_s [pg * NB + b] = s;
                g_s2[pg * NB + b] = ss;
            }
        }

        gbar(G, band, band);      // all band stats visible; reset its ticket

        // ================= APPLY phase (ticketed) =================
        for (;;) {
            if (tx == 0) s_u = atomicAdd(&g_tick[NBANDS + band], 1);
            __syncthreads();
            const int u = s_u;
            __syncthreads();
            if (u >= NU) break;

            const int qtr = u & 3;
            const int sy  = band * BPH + ((u >> 2) & 15);
            const int b   = u >> 6;

            // --- per-unit code computation: 16 patches x 16 threads ---
            {
                const int pi = tx >> 4;       // local patch
                const int bj = tx & 15;       // handles batches bj, bj+16
                const int pg = sy * 64 + qtr * 16 + pi;
                float qsum = 0.f, msum = 0.f;
#pragma unroll
                for (int k = 0; k < 2; ++k) {
                    const int bb = bj + k * 16;
                    float s  = g_s [pg * NB + bb];
                    float ss = g_s2[pg * NB + bb];
                    float mean = s * (1.0f / 256.0f);
                    float var  = (ss - s * s * (1.0f / 256.0f)) * (1.0f / 255.0f);
                    var = fmaxf(var, 0.0f);
                    float iq = 1.0f - 2.0f * fabsf(mean - 0.5f);
                    qsum += (sqrtf(var) + iq + var) * (1.0f / 3.0f);
                    msum += mean;
                }
#pragma unroll
                for (int off = 8; off >= 1; off >>= 1) {
                    qsum += __shfl_down_sync(0xffffffffu, qsum, off, 16);
                    msum += __shfl_down_sync(0xffffffffu, msum, off, 16);
                }
                if (bj == 0) {
                    float q = qsum * (1.0f / NB);
                    float m = msum * (1.0f / NB);

                    bool low    = q < 0.7f;
                    bool strong = low  && (r_strong[pg] < 0.8f);
                    bool drop   = low  && (q < 0.3f) && (r_drop[pg] < 0.1f);
                    bool els    = !low && (r_else[pg] < 0.3f);

                    int code = 0;
                    if (strong) code = aug_choice[pg] + 1;
                    if (els)    code = slight_choice[pg] + 5;
                    if (drop)   code = 7;

                    float alpha = 1.f, beta = 0.f, delta = 0.f;
                    if      (code == 1) beta = 0.1f;
                    else if (code == 3) alpha = bright_f[pg];
                    else if (code == 4) { float cf = contrast_f[pg]; alpha = cf; delta = m * (1.0f - cf); }
                    else if (code == 5) beta = 0.05f;
                    else if (code == 6) alpha = slight_f[pg];
                    else if (code == 7) alpha = 0.f;

                    s_code[pi] = code;
                    s_al[pi] = alpha; s_be[pi] = beta; s_de[pi] = delta;
                }
            }
            __syncthreads();

            // --- apply: front-batched L2-hot loads, register blur, stcs ---
            const int x = qtr * 256 + tx;
            const size_t base = (size_t)b * IMGSZ + (size_t)(sy * PS) * IW + x;

            float v[PS];
#pragma unroll
            for (int y = 0; y < PS; ++y)
                v[y] = img[base + (size_t)y * IW];

            const int   lp   = tx >> 4;
            const int   code = s_code[lp];
            const float al   = s_al[lp];
            const float be   = s_be[lp];
            const float de   = s_de[lp];
            const int   lx   = tx & 15;
            const unsigned gmask = 0xFFFFu << (tx & 16);

            float r[PS];
            if (code == 2) {
                float hs[PS];
#pragma unroll
                for (int y = 0; y < PS; ++y) {
                    float l  = __shfl_up_sync  (gmask, v[y], 1, 16);
                    float rr = __shfl_down_sync(gmask, v[y], 1, 16);
                    if (lx == 0)  l  = 0.0f;
                    if (lx == 15) rr = 0.0f;
                    hs[y] = v[y] + l + rr;
                }
#pragma unroll
                for (int y = 0; y < PS; ++y) {
                    float sum = hs[y];
                    if (y > 0)      sum += hs[y - 1];
                    if (y < PS - 1) sum += hs[y + 1];
                    r[y] = sum * (1.0f / 9.0f);
                }
            } else if (be != 0.0f) {
                float n[PS];
#pragma unroll
                for (int y = 0; y < PS; ++y)
                    n[y] = noise[base + (size_t)y * IW];
#pragma unroll
                for (int y = 0; y < PS; ++y)
                    r[y] = clamp01(fmaf(be, n[y], fmaf(al, v[y], de)));
            } else {
#pragma unroll
                for (int y = 0; y < PS; ++y)
                    r[y] = clamp01(fmaf(al, v[y], de));
            }
#pragma unroll
            for (int y = 0; y < PS; ++y)
                __stcs(&out[base + (size_t)y * IW], r[y]);

            __syncthreads();      // s_code reuse guard for next unit
        }
    }

    gbar(G, NBANDS, 2 * NBANDS - 1);   // reset apply tickets for next launch
}

extern "C" void kernel_launch(void* const* d_in, const int* in_sizes, int n_in,
                              void* d_out, int out_size) {
    const float* img           = (const float*)d_in[0];
    const float* noise         = (const float*)d_in[1];
    const float* r_strong      = (const float*)d_in[2];
    const float* r_drop        = (const float*)d_in[3];
    const float* r_else        = (const float*)d_in[4];
    const float* bright_f      = (const float*)d_in[5];
    const float* contrast_f    = (const float*)d_in[6];
    const float* slight_f      = (const float*)d_in[7];
    const int*   aug_choice    = (const int*)d_in[8];
    const int*   slight_choice = (const int*)d_in[9];
    float* out = (float*)d_out;

    int dev = 0, nsm = 0, nb = 0;
    cudaGetDevice(&dev);
    cudaDeviceGetAttribute(&nsm, cudaDevAttrMultiProcessorCount, dev);
    cudaOccupancyMaxActiveBlocksPerMultiprocessor(&nb, persist_kernel, 256, 0);
    if (nb < 1) nb = 1;                 // defensive; residency is the contract
    int G = nsm * nb;
    if (G > NU) G = NU;                 // never more CTAs than units

    persist_kernel<<<G, 256>>>(img, noise, r_strong, r_drop, r_else,
                               bright_f, contrast_f, slight_f,
                               aug_choice, slight_choice, out, G);
}

// round 13
// speedup vs baseline: 1.6457x; 1.6457x over previous
#include <cuda_runtime.h>
#include <math.h>

#define PS 16
#define NB 32
#define IMGSZ (1024*1024)

__device__ __forceinline__ float clamp01(float x) {
    return fminf(fmaxf(x, 0.0f), 1.0f);
}

// ---------------------------------------------------------------------------
// One CTA = one patch, all 32 batches, float4 everywhere, no big stats tile.
// Thread t: c4 = t&3 (16B chunk of a row), slot = t>>2, r = slot&15 (row),
// s4 = slot>>4 (batch phase). Thread owns chunk (r,c4) of batches 4k+s4,
// k=0..7 -> v[8] float4 (32 regs). 4 lanes cover one full 64B patch row.
//  stats: in-register (sum,sumsq) per float4 -> padded smem partials ->
//         one warp finalizes 32 batch stats (conflict-free).
//  code : thread 0 -> affine (alpha,beta,delta) / blur flag (CTA-uniform).
//  apply: float4 streaming stores from registers; blur (rare, uniform)
//         stages half the batches at a time through the union buffer.
// ---------------------------------------------------------------------------
__global__ void __launch_bounds__(256, 4)
fused_kernel(const float* __restrict__ img,
             const float* __restrict__ noise,
             const float* __restrict__ r_strong,
             const float* __restrict__ r_drop,
             const float* __restrict__ r_else,
             const float* __restrict__ bright_f,
             const float* __restrict__ contrast_f,
             const float* __restrict__ slight_f,
             const int*   __restrict__ aug_choice,
             const int*   __restrict__ slight_choice,
             float* __restrict__ out) {
    // union: [0..2080) psum[32][65], [2080..4160) psq[32][65]  (stats)
    //        [0..6400) blur tile [16][16][20]                  (apply, blur)
    __shared__ float ubuf[6400];
    __shared__ float s_q[NB], s_m[NB];
    __shared__ int   s_code;
    __shared__ float s_al, s_be, s_de;

    const int p   = blockIdx.x;              // patch 0..4095
    const int sy  = p >> 6;
    const int px  = p & 63;
    const int t   = threadIdx.x;
    const int c4  = t & 3;                   // 16B chunk in row
    const int slot = t >> 2;
    const int r   = slot & 15;               // patch row
    const int s4  = slot >> 4;               // batch phase 0..3

    const int gofs = (sy * PS + r) * 1024 + px * PS + c4 * 4;

    // ---- Phase 1: 8 front-batched LDG.128 (batches 4k+s4) ----
    float4 v[8];
#pragma unroll
    for (int k = 0; k < 8; ++k)
        v[k] = *reinterpret_cast<const float4*>(
                   img + (size_t)(4 * k + s4) * IMGSZ + gofs);

    // ---- Phase 2: in-register partials -> smem (conflict-free) ----
    float* psum = ubuf;
    float* psq  = ubuf + 2080;
#pragma unroll
    for (int k = 0; k < 8; ++k) {
        const int b = 4 * k + s4;
        float s  = (v[k].x + v[k].y) + (v[k].z + v[k].w);
        float ss = fmaf(v[k].x, v[k].x,
                   fmaf(v[k].y, v[k].y,
                   fmaf(v[k].z, v[k].z, v[k].w * v[k].w)));
        psum[b * 65 + r * 4 + c4] = s;
        psq [b * 65 + r * 4 + c4] = ss;
    }
    __syncthreads();

    if (t < NB) {                            // one warp: batch t
        float s = 0.f, ss = 0.f;
#pragma unroll
        for (int j = 0; j < 64; ++j) {
            s  += psum[t * 65 + j];
            ss += psq [t * 65 + j];
        }
        float mean = s * (1.0f / 256.0f);
        float var  = (ss - s * s * (1.0f / 256.0f)) * (1.0f / 255.0f); // ddof=1
        var = fmaxf(var, 0.0f);
        float std_ = sqrtf(var);
        float iq   = 1.0f - 2.0f * fabsf(mean - 0.5f);
        s_q[t] = (std_ + iq + var) * (1.0f / 3.0f);
        s_m[t] = mean;
    }
    __syncthreads();

    // ---- Phase 3: code (thread 0, CTA-uniform) ----
    if (t == 0) {
        float q = 0.f, m = 0.f;
#pragma unroll
        for (int b = 0; b < NB; ++b) { q += s_q[b]; m += s_m[b]; }
        q *= (1.0f / NB);
        m *= (1.0f / NB);

        bool low    = q < 0.7f;
        bool strong = low  && (r_strong[p] < 0.8f);
        bool drop   = low  && (q < 0.3f) && (r_drop[p] < 0.1f);
        bool els    = !low && (r_else[p] < 0.3f);

        int code = 0;
        if (strong) code = aug_choice[p] + 1;      // 1..4
        if (els)    code = slight_choice[p] + 5;   // 5..6
        if (drop)   code = 7;

        float alpha = 1.f, beta = 0.f, delta = 0.f;
        if      (code == 1) beta = 0.1f;
        else if (code == 3) alpha = bright_f[p];
        else if (code == 4) { float cf = contrast_f[p]; alpha = cf; delta = m * (1.0f - cf); }
        else if (code == 5) beta = 0.05f;
        else if (code == 6) alpha = slight_f[p];
        else if (code == 7) alpha = 0.f;

        s_code = code; s_al = alpha; s_be = beta; s_de = delta;
    }
    __syncthreads();

    const int   code = s_code;               // uniform across CTA
    const float al   = s_al;
    const float be   = s_be;
    const float de   = s_de;

    // ---- Phase 4: apply + STG.128 streaming stores ----
    if (code == 2) {
        // blur: stage 16 batches at a time through the union buffer
#pragma unroll
        for (int h = 0; h < 2; ++h) {
            __syncthreads();                 // prior readers done (h=1 guard)
#pragma unroll
            for (int k = 4 * h; k < 4 * h + 4; ++k) {
                const int bl = (4 * k + s4) - 16 * h;   // 0..15
                *reinterpret_cast<float4*>(ubuf + bl * 320 + r * 20 + c4 * 4) = v[k];
            }
            __syncthreads();
#pragma unroll
            for (int k = 4 * h; k < 4 * h + 4; ++k) {
                const int bl = (4 * k + s4) - 16 * h;
                const float* tb = ubuf + bl * 320;
                float rs[4];
#pragma unroll
                for (int j = 0; j < 4; ++j) {
                    const int cc0 = c4 * 4 + j;
                    float sum = 0.f;
#pragma unroll
                    for (int dy = -1; dy <= 1; ++dy) {
                        const int rr = r + dy;
                        if (rr < 0 || rr >= PS) continue;
#pragma unroll
                        for (int dx = -1; dx <= 1; ++dx) {
                            const int cc = cc0 + dx;
                            if (cc < 0 || cc >= PS) continue;
                            sum += tb[rr * 20 + cc];
                        }
                    }
                    rs[j] = sum * (1.0f / 9.0f);
                }
                __stcs(reinterpret_cast<float4*>(
                           out + (size_t)(4 * k + s4) * IMGSZ + gofs),
                       make_float4(rs[0], rs[1], rs[2], rs[3]));
            }
        }
    } else if (be != 0.0f) {
#pragma unroll
        for (int k0 = 0; k0 < 8; k0 += 4) {
            float4 n[4];
#pragma unroll
            for (int kk = 0; kk < 4; ++kk)
                n[kk] = *reinterpret_cast<const float4*>(
                            noise + (size_t)(4 * (k0 + kk) + s4) * IMGSZ + gofs);
#pragma unroll
            for (int kk = 0; kk < 4; ++kk) {
                const int k = k0 + kk;
                float4 o;
                o.x = clamp01(fmaf(be, n[kk].x, fmaf(al, v[k].x, de)));
                o.y = clamp01(fmaf(be, n[kk].y, fmaf(al, v[k].y, de)));
                o.z = clamp01(fmaf(be, n[kk].z, fmaf(al, v[k].z, de)));
                o.w = clamp01(fmaf(be, n[kk].w, fmaf(al, v[k].w, de)));
                __stcs(reinterpret_cast<float4*>(
                           out + (size_t)(4 * k + s4) * IMGSZ + gofs), o);
            }
        }
    } else {
#pragma unroll
        for (int k = 0; k < 8; ++k) {
            float4 o;
            o.x = clamp01(fmaf(al, v[k].x, de));
            o.y = clamp01(fmaf(al, v[k].y, de));
            o.z = clamp01(fmaf(al, v[k].z, de));
            o.w = clamp01(fmaf(al, v[k].w, de));
            __stcs(reinterpret_cast<float4*>(
                       out + (size_t)(4 * k + s4) * IMGSZ + gofs), o);
        }
    }
}

extern "C" void kernel_launch(void* const* d_in, const int* in_sizes, int n_in,
                              void* d_out, int out_size) {
    const float* img           = (const float*)d_in[0];
    const float* noise         = (const float*)d_in[1];
    const float* r_strong      = (const float*)d_in[2];
    const float* r_drop        = (const float*)d_in[3];
    const float* r_else        = (const float*)d_in[4];
    const float* bright_f      = (const float*)d_in[5];
    const float* contrast_f    = (const float*)d_in[6];
    const float* slight_f      = (const float*)d_in[7];
    const int*   aug_choice    = (const int*)d_in[8];
    const int*   slight_choice = (const int*)d_in[9];
    float* out = (float*)d_out;

    fused_kernel<<<4096, 256>>>(img, noise, r_strong, r_drop, r_else,
                                bright_f, contrast_f, slight_f,
                                aug_choice, slight_choice, out);
}